// round 1
// baseline (speedup 1.0000x reference)
#include <cuda_runtime.h>

// ScaledDotProductAttention: B=4 H=16 S=2048 D=64
// outputs: output [B,H,S,D] then attn [B,H,S,S], concatenated in d_out.

#define S_LEN 2048
#define D_DIM 64
#define BH 64          // B*H
#define TEMP_INV 0.125f

// ---------------------------------------------------------------------------
// Kernel 1: scores = (q/8) @ k^T   per (b,h) head.  64x64 tile, 4x4 micro.
// ---------------------------------------------------------------------------
__global__ __launch_bounds__(256) void qk_kernel(const float* __restrict__ q,
                                                 const float* __restrict__ k,
                                                 float* __restrict__ attn) {
    __shared__ float Qs[64][65];
    __shared__ float Ks[64][65];

    const int bh = blockIdx.z;
    const int tid = threadIdx.x;

    const float* qb = q + ((size_t)bh * S_LEN + (size_t)blockIdx.y * 64) * D_DIM;
    const float* kb = k + ((size_t)bh * S_LEN + (size_t)blockIdx.x * 64) * D_DIM;

    // Load 64x64 Q tile (scaled) and 64x64 K tile. 256 threads x 4 iters x float4.
#pragma unroll
    for (int e = tid * 4; e < 64 * 64; e += 256 * 4) {
        int row = e >> 6;
        int col = e & 63;
        float4 a = *(const float4*)(qb + row * D_DIM + col);
        Qs[row][col + 0] = a.x * TEMP_INV;
        Qs[row][col + 1] = a.y * TEMP_INV;
        Qs[row][col + 2] = a.z * TEMP_INV;
        Qs[row][col + 3] = a.w * TEMP_INV;
        float4 b = *(const float4*)(kb + row * D_DIM + col);
        Ks[row][col + 0] = b.x;
        Ks[row][col + 1] = b.y;
        Ks[row][col + 2] = b.z;
        Ks[row][col + 3] = b.w;
    }
    __syncthreads();

    const int tx = tid & 15;
    const int ty = tid >> 4;
    const int r0 = ty * 4;
    const int c0 = tx * 4;

    float acc[4][4] = {};
#pragma unroll
    for (int d = 0; d < D_DIM; d++) {
        float a0 = Qs[r0 + 0][d];
        float a1 = Qs[r0 + 1][d];
        float a2 = Qs[r0 + 2][d];
        float a3 = Qs[r0 + 3][d];
        float b0 = Ks[c0 + 0][d];
        float b1 = Ks[c0 + 1][d];
        float b2 = Ks[c0 + 2][d];
        float b3 = Ks[c0 + 3][d];
        acc[0][0] += a0 * b0; acc[0][1] += a0 * b1; acc[0][2] += a0 * b2; acc[0][3] += a0 * b3;
        acc[1][0] += a1 * b0; acc[1][1] += a1 * b1; acc[1][2] += a1 * b2; acc[1][3] += a1 * b3;
        acc[2][0] += a2 * b0; acc[2][1] += a2 * b1; acc[2][2] += a2 * b2; acc[2][3] += a2 * b3;
        acc[3][0] += a3 * b0; acc[3][1] += a3 * b1; acc[3][2] += a3 * b2; acc[3][3] += a3 * b3;
    }

    float* cb = attn + ((size_t)bh * S_LEN + (size_t)blockIdx.y * 64) * S_LEN
                     + (size_t)blockIdx.x * 64;
#pragma unroll
    for (int i = 0; i < 4; i++) {
        float4 o;
        o.x = acc[i][0]; o.y = acc[i][1]; o.z = acc[i][2]; o.w = acc[i][3];
        *(float4*)(cb + (size_t)(r0 + i) * S_LEN + c0) = o;
    }
}

// ---------------------------------------------------------------------------
// Kernel 2: row-wise softmax in place. One block (256 thr) per row of 2048.
// ---------------------------------------------------------------------------
__global__ __launch_bounds__(256) void softmax_kernel(float* __restrict__ attn) {
    const size_t row = blockIdx.x;
    float* p = attn + row * (size_t)S_LEN;
    const int tid = threadIdx.x;
    const int lane = tid & 31;
    const int warp = tid >> 5;

    float4 v0 = *(const float4*)(p + tid * 4);
    float4 v1 = *(const float4*)(p + 1024 + tid * 4);

    __shared__ float red[8];

    // --- row max ---
    float m = fmaxf(fmaxf(fmaxf(v0.x, v0.y), fmaxf(v0.z, v0.w)),
                    fmaxf(fmaxf(v1.x, v1.y), fmaxf(v1.z, v1.w)));
#pragma unroll
    for (int off = 16; off > 0; off >>= 1)
        m = fmaxf(m, __shfl_xor_sync(0xffffffffu, m, off));
    if (lane == 0) red[warp] = m;
    __syncthreads();
    float m0 = red[0];
#pragma unroll
    for (int w = 1; w < 8; w++) m0 = fmaxf(m0, red[w]);
    __syncthreads();

    // --- exp + sum ---
    v0.x = __expf(v0.x - m0); v0.y = __expf(v0.y - m0);
    v0.z = __expf(v0.z - m0); v0.w = __expf(v0.w - m0);
    v1.x = __expf(v1.x - m0); v1.y = __expf(v1.y - m0);
    v1.z = __expf(v1.z - m0); v1.w = __expf(v1.w - m0);

    float s = (v0.x + v0.y) + (v0.z + v0.w) + (v1.x + v1.y) + (v1.z + v1.w);
#pragma unroll
    for (int off = 16; off > 0; off >>= 1)
        s += __shfl_xor_sync(0xffffffffu, s, off);
    if (lane == 0) red[warp] = s;
    __syncthreads();
    float s0 = red[0];
#pragma unroll
    for (int w = 1; w < 8; w++) s0 += red[w];

    const float inv = 1.0f / s0;
    v0.x *= inv; v0.y *= inv; v0.z *= inv; v0.w *= inv;
    v1.x *= inv; v1.y *= inv; v1.z *= inv; v1.w *= inv;

    *(float4*)(p + tid * 4) = v0;
    *(float4*)(p + 1024 + tid * 4) = v1;
}

// ---------------------------------------------------------------------------
// Kernel 3: out = attn @ v.   M=2048 (tiled 64), N=64, K=2048 (tiled 64).
// ---------------------------------------------------------------------------
__global__ __launch_bounds__(256) void pv_kernel(const float* __restrict__ attn,
                                                 const float* __restrict__ v,
                                                 float* __restrict__ out) {
    __shared__ float As[64][65];
    __shared__ float Vs[64][65];

    const int bh = blockIdx.y;
    const int tid = threadIdx.x;
    const int tx = tid & 15;
    const int ty = tid >> 4;
    const int r0 = ty * 4;
    const int c0 = tx * 4;

    const float* ab = attn + ((size_t)bh * S_LEN + (size_t)blockIdx.x * 64) * S_LEN;
    const float* vb = v + (size_t)bh * S_LEN * D_DIM;

    float acc[4][4] = {};

    for (int kt = 0; kt < S_LEN; kt += 64) {
#pragma unroll
        for (int e = tid * 4; e < 64 * 64; e += 256 * 4) {
            int row = e >> 6;
            int col = e & 63;
            float4 a = *(const float4*)(ab + (size_t)row * S_LEN + kt + col);
            As[row][col + 0] = a.x;
            As[row][col + 1] = a.y;
            As[row][col + 2] = a.z;
            As[row][col + 3] = a.w;
            float4 b = *(const float4*)(vb + (size_t)(kt + row) * D_DIM + col);
            Vs[row][col + 0] = b.x;
            Vs[row][col + 1] = b.y;
            Vs[row][col + 2] = b.z;
            Vs[row][col + 3] = b.w;
        }
        __syncthreads();

#pragma unroll
        for (int kk = 0; kk < 64; kk++) {
            float a0 = As[r0 + 0][kk];
            float a1 = As[r0 + 1][kk];
            float a2 = As[r0 + 2][kk];
            float a3 = As[r0 + 3][kk];
            float b0 = Vs[kk][c0 + 0];
            float b1 = Vs[kk][c0 + 1];
            float b2 = Vs[kk][c0 + 2];
            float b3 = Vs[kk][c0 + 3];
            acc[0][0] += a0 * b0; acc[0][1] += a0 * b1; acc[0][2] += a0 * b2; acc[0][3] += a0 * b3;
            acc[1][0] += a1 * b0; acc[1][1] += a1 * b1; acc[1][2] += a1 * b2; acc[1][3] += a1 * b3;
            acc[2][0] += a2 * b0; acc[2][1] += a2 * b1; acc[2][2] += a2 * b2; acc[2][3] += a2 * b3;
            acc[3][0] += a3 * b0; acc[3][1] += a3 * b1; acc[3][2] += a3 * b2; acc[3][3] += a3 * b3;
        }
        __syncthreads();
    }

    float* ob = out + ((size_t)bh * S_LEN + (size_t)blockIdx.x * 64) * D_DIM;
#pragma unroll
    for (int i = 0; i < 4; i++) {
        float4 o;
        o.x = acc[i][0]; o.y = acc[i][1]; o.z = acc[i][2]; o.w = acc[i][3];
        *(float4*)(ob + (size_t)(r0 + i) * D_DIM + c0) = o;
    }
}

// ---------------------------------------------------------------------------
extern "C" void kernel_launch(void* const* d_in, const int* in_sizes, int n_in,
                              void* d_out, int out_size) {
    const float* q = (const float*)d_in[0];
    const float* k = (const float*)d_in[1];
    const float* v = (const float*)d_in[2];

    float* out = (float*)d_out;                             // [BH, S, D]
    float* attn = out + (size_t)BH * S_LEN * D_DIM;         // [BH, S, S]

    qk_kernel<<<dim3(S_LEN / 64, S_LEN / 64, BH), 256>>>(q, k, attn);
    softmax_kernel<<<dim3(BH * S_LEN), 256>>>(attn);
    pv_kernel<<<dim3(S_LEN / 64, BH), 256>>>(attn, v, out);
}

// round 2
// speedup vs baseline: 1.5920x; 1.5920x over previous
#include <cuda_runtime.h>
#include <cuda_bf16.h>
#include <mma.h>

using namespace nvcuda;

#define S_LEN 2048
#define D_DIM 64
#define BH 64
#define TEMP_INV 0.125f
#define PAD 72      // bf16 tile row stride (elements)
#define SPAD 68     // fp32 score tile row stride (elements)

__device__ float g_rowsum[BH * S_LEN];

__device__ __forceinline__ void split_bf16(float x, __nv_bfloat16& hi, __nv_bfloat16& lo) {
    hi = __float2bfloat16(x);
    lo = __float2bfloat16(x - __bfloat162float(hi));
}

// ---------------------------------------------------------------------------
// Kernel A: e = exp((q/8) @ k^T), row-block owns full row; accumulates rowsum.
// smem layout (bytes):
//   [0      , 9216 )  Qhi   64xPAD bf16
//   [9216   , 18432)  Qlo
//   [18432  , 27648)  Khi        } overlaid by Stile (64 x SPAD fp32 = 17408B)
//   [27648  , 36864)  Klo        }
//   [36864  , 37888)  rowpart 64x4 fp32
// ---------------------------------------------------------------------------
__global__ __launch_bounds__(256) void qk_exp_kernel(const float* __restrict__ q,
                                                     const float* __restrict__ k,
                                                     float* __restrict__ attn) {
    __shared__ __align__(16) char sm[37888];
    __nv_bfloat16* Qhi = (__nv_bfloat16*)sm;
    __nv_bfloat16* Qlo = Qhi + 64 * PAD;
    __nv_bfloat16* Khi = (__nv_bfloat16*)(sm + 18432);
    __nv_bfloat16* Klo = Khi + 64 * PAD;
    float* Stile = (float*)(sm + 18432);      // overlays Khi/Klo
    float* rowpart = (float*)(sm + 36864);    // [64][4]

    const int bh = blockIdx.y;
    const int m0 = blockIdx.x * 64;
    const int tid = threadIdx.x;
    const int warp = tid >> 5;
    const int wr = warp >> 1;          // 0..3: 16-row band
    const int wc = (warp & 1) * 2;     // 0 or 2: first of two 16-col tiles

    rowpart[tid] = 0.0f;

    // Load + scale + split Q tile (64x64)
    const float* qb = q + ((size_t)bh * S_LEN + m0) * D_DIM;
    for (int i = tid; i < 1024; i += 256) {
        int row = i >> 4;
        int c4 = (i & 15) * 4;
        float4 a = *(const float4*)(qb + row * D_DIM + c4);
        a.x *= TEMP_INV; a.y *= TEMP_INV; a.z *= TEMP_INV; a.w *= TEMP_INV;
        split_bf16(a.x, Qhi[row * PAD + c4 + 0], Qlo[row * PAD + c4 + 0]);
        split_bf16(a.y, Qhi[row * PAD + c4 + 1], Qlo[row * PAD + c4 + 1]);
        split_bf16(a.z, Qhi[row * PAD + c4 + 2], Qlo[row * PAD + c4 + 2]);
        split_bf16(a.w, Qhi[row * PAD + c4 + 3], Qlo[row * PAD + c4 + 3]);
    }
    __syncthreads();

    const float* kbase = k + (size_t)bh * S_LEN * D_DIM;
    float* arow = attn + ((size_t)bh * S_LEN + m0) * S_LEN;

    for (int kt = 0; kt < 32; kt++) {
        // Load + split K tile (64 cols of scores x 64 d)
        const float* kb = kbase + (size_t)kt * 64 * D_DIM;
        for (int i = tid; i < 1024; i += 256) {
            int row = i >> 4;
            int c4 = (i & 15) * 4;
            float4 a = *(const float4*)(kb + row * D_DIM + c4);
            split_bf16(a.x, Khi[row * PAD + c4 + 0], Klo[row * PAD + c4 + 0]);
            split_bf16(a.y, Khi[row * PAD + c4 + 1], Klo[row * PAD + c4 + 1]);
            split_bf16(a.z, Khi[row * PAD + c4 + 2], Klo[row * PAD + c4 + 2]);
            split_bf16(a.w, Khi[row * PAD + c4 + 3], Klo[row * PAD + c4 + 3]);
        }
        __syncthreads();

        wmma::fragment<wmma::accumulator, 16, 16, 16, float> acc[2];
        wmma::fill_fragment(acc[0], 0.0f);
        wmma::fill_fragment(acc[1], 0.0f);

#pragma unroll
        for (int kk = 0; kk < 4; kk++) {
            wmma::fragment<wmma::matrix_a, 16, 16, 16, __nv_bfloat16, wmma::row_major> ahi, alo;
            wmma::load_matrix_sync(ahi, Qhi + (wr * 16) * PAD + kk * 16, PAD);
            wmma::load_matrix_sync(alo, Qlo + (wr * 16) * PAD + kk * 16, PAD);
#pragma unroll
            for (int n = 0; n < 2; n++) {
                wmma::fragment<wmma::matrix_b, 16, 16, 16, __nv_bfloat16, wmma::col_major> bhi, blo;
                wmma::load_matrix_sync(bhi, Khi + ((wc + n) * 16) * PAD + kk * 16, PAD);
                wmma::load_matrix_sync(blo, Klo + ((wc + n) * 16) * PAD + kk * 16, PAD);
                wmma::mma_sync(acc[n], ahi, bhi, acc[n]);
                wmma::mma_sync(acc[n], ahi, blo, acc[n]);
                wmma::mma_sync(acc[n], alo, bhi, acc[n]);
            }
        }
        __syncthreads();   // all warps done reading K before Stile overlay write

        wmma::store_matrix_sync(Stile + (wr * 16) * SPAD + wc * 16, acc[0], SPAD, wmma::mem_row_major);
        wmma::store_matrix_sync(Stile + (wr * 16) * SPAD + (wc + 1) * 16, acc[1], SPAD, wmma::mem_row_major);
        __syncthreads();

        // Epilogue: exp + rowsum partials + write unnormalized e
        {
            const int row = tid >> 2;
            const int c0 = (tid & 3) * 16;
            float part = 0.0f;
            float* dst = arow + (size_t)row * S_LEN + kt * 64 + c0;
            const float* srcp = Stile + row * SPAD + c0;
#pragma unroll
            for (int j = 0; j < 16; j += 4) {
                float4 sv = *(const float4*)(srcp + j);
                sv.x = __expf(fminf(sv.x, 80.0f));
                sv.y = __expf(fminf(sv.y, 80.0f));
                sv.z = __expf(fminf(sv.z, 80.0f));
                sv.w = __expf(fminf(sv.w, 80.0f));
                part += (sv.x + sv.y) + (sv.z + sv.w);
                *(float4*)(dst + j) = sv;
            }
            rowpart[row * 4 + (tid & 3)] += part;
        }
        __syncthreads();   // Stile consumed before next K tile overwrites it
    }

    if (tid < 64) {
        float s = rowpart[tid * 4 + 0] + rowpart[tid * 4 + 1]
                + rowpart[tid * 4 + 2] + rowpart[tid * 4 + 3];
        g_rowsum[(size_t)bh * S_LEN + m0 + tid] = s;
    }
}

// ---------------------------------------------------------------------------
// Kernel B: normalize attn in place; out = attn_norm @ v  (bf16-split wmma).
// smem: Phi/Plo/Vhi/Vlo each 64xPAD bf16 (9216B) + inv[64] fp32.
// ---------------------------------------------------------------------------
__global__ __launch_bounds__(256) void pv_kernel(float* __restrict__ attn,
                                                 const float* __restrict__ v,
                                                 float* __restrict__ out) {
    __shared__ __align__(16) char sm[36864 + 256];
    __nv_bfloat16* Phi = (__nv_bfloat16*)sm;
    __nv_bfloat16* Plo = Phi + 64 * PAD;
    __nv_bfloat16* Vhi = Plo + 64 * PAD;
    __nv_bfloat16* Vlo = Vhi + 64 * PAD;
    float* inv = (float*)(sm + 36864);

    const int bh = blockIdx.y;
    const int m0 = blockIdx.x * 64;
    const int tid = threadIdx.x;
    const int warp = tid >> 5;
    const int wr = warp >> 1;
    const int wc = (warp & 1) * 2;

    if (tid < 64)
        inv[tid] = __frcp_rn(g_rowsum[(size_t)bh * S_LEN + m0 + tid]);
    __syncthreads();

    float* arow = attn + ((size_t)bh * S_LEN + m0) * S_LEN;
    const float* vb = v + (size_t)bh * S_LEN * D_DIM;

    wmma::fragment<wmma::accumulator, 16, 16, 16, float> acc[2];
    wmma::fill_fragment(acc[0], 0.0f);
    wmma::fill_fragment(acc[1], 0.0f);

    for (int kt = 0; kt < 32; kt++) {
        // Load e tile, normalize, write back, split to bf16
        for (int i = tid; i < 1024; i += 256) {
            int row = i >> 4;
            int c4 = (i & 15) * 4;
            float* ap = arow + (size_t)row * S_LEN + kt * 64 + c4;
            float4 a = *(const float4*)ap;
            float iv = inv[row];
            a.x *= iv; a.y *= iv; a.z *= iv; a.w *= iv;
            *(float4*)ap = a;
            split_bf16(a.x, Phi[row * PAD + c4 + 0], Plo[row * PAD + c4 + 0]);
            split_bf16(a.y, Phi[row * PAD + c4 + 1], Plo[row * PAD + c4 + 1]);
            split_bf16(a.z, Phi[row * PAD + c4 + 2], Plo[row * PAD + c4 + 2]);
            split_bf16(a.w, Phi[row * PAD + c4 + 3], Plo[row * PAD + c4 + 3]);
        }
        // Load V tile, split
        for (int i = tid; i < 1024; i += 256) {
            int row = i >> 4;
            int c4 = (i & 15) * 4;
            float4 a = *(const float4*)(vb + (size_t)(kt * 64 + row) * D_DIM + c4);
            split_bf16(a.x, Vhi[row * PAD + c4 + 0], Vlo[row * PAD + c4 + 0]);
            split_bf16(a.y, Vhi[row * PAD + c4 + 1], Vlo[row * PAD + c4 + 1]);
            split_bf16(a.z, Vhi[row * PAD + c4 + 2], Vlo[row * PAD + c4 + 2]);
            split_bf16(a.w, Vhi[row * PAD + c4 + 3], Vlo[row * PAD + c4 + 3]);
        }
        __syncthreads();

#pragma unroll
        for (int kk = 0; kk < 4; kk++) {
            wmma::fragment<wmma::matrix_a, 16, 16, 16, __nv_bfloat16, wmma::row_major> ahi, alo;
            wmma::load_matrix_sync(ahi, Phi + (wr * 16) * PAD + kk * 16, PAD);
            wmma::load_matrix_sync(alo, Plo + (wr * 16) * PAD + kk * 16, PAD);
#pragma unroll
            for (int n = 0; n < 2; n++) {
                wmma::fragment<wmma::matrix_b, 16, 16, 16, __nv_bfloat16, wmma::row_major> bhi, blo;
                wmma::load_matrix_sync(bhi, Vhi + (kk * 16) * PAD + (wc + n) * 16, PAD);
                wmma::load_matrix_sync(blo, Vlo + (kk * 16) * PAD + (wc + n) * 16, PAD);
                wmma::mma_sync(acc[n], ahi, bhi, acc[n]);
                wmma::mma_sync(acc[n], ahi, blo, acc[n]);
                wmma::mma_sync(acc[n], alo, bhi, acc[n]);
            }
        }
        __syncthreads();
    }

    float* ob = out + ((size_t)bh * S_LEN + m0) * D_DIM;
    wmma::store_matrix_sync(ob + (wr * 16) * D_DIM + wc * 16, acc[0], D_DIM, wmma::mem_row_major);
    wmma::store_matrix_sync(ob + (wr * 16) * D_DIM + (wc + 1) * 16, acc[1], D_DIM, wmma::mem_row_major);
}

// ---------------------------------------------------------------------------
extern "C" void kernel_launch(void* const* d_in, const int* in_sizes, int n_in,
                              void* d_out, int out_size) {
    const float* q = (const float*)d_in[0];
    const float* k = (const float*)d_in[1];
    const float* v = (const float*)d_in[2];

    float* out = (float*)d_out;                          // [BH, S, D]
    float* attn = out + (size_t)BH * S_LEN * D_DIM;      // [BH, S, S]

    qk_exp_kernel<<<dim3(S_LEN / 64, BH), 256>>>(q, k, attn);
    pv_kernel<<<dim3(S_LEN / 64, BH), 256>>>(attn, v, out);
}